// round 1
// baseline (speedup 1.0000x reference)
#include <cuda_runtime.h>
#include <cstdint>
#include <cstddef>

// Problem sizes
#define TSTEPS 64
#define BATCH  1024
#define OBSD   8
#define HID    512
#define M_ALL  (TSTEPS*BATCH)   // 65536

// ---------------------------------------------------------------------------
// Scratch buffers (static __device__ globals — no allocation allowed)
// ---------------------------------------------------------------------------
__device__ float g_h    [(size_t)M_ALL*HID];   // RK4 state (init = hs), ends as h_ode
__device__ float g_heval[(size_t)M_ALL*HID];   // intermediate eval point h + c*k
__device__ float g_z1   [(size_t)M_ALL*HID];
__device__ float g_z2   [(size_t)M_ALL*HID];
__device__ float g_kacc [(size_t)M_ALL*HID];
__device__ float g_gi   [(size_t)M_ALL*3*HID]; // GRU input gates for all T
__device__ float g_gh   [(size_t)BATCH*3*HID];
__device__ float g_hst  [(size_t)BATCH*HID];   // GRU recurrent state

// ---------------------------------------------------------------------------
// packed f32x2 helpers (sm_103a dual-rate fp32 path; plain FFMA is rt=2/SMSP)
// ---------------------------------------------------------------------------
static __device__ __forceinline__ unsigned long long pk2(float x, float y){
    unsigned long long r;
    asm("mov.b64 %0, {%1,%2};" : "=l"(r) : "f"(x), "f"(y));
    return r;
}
static __device__ __forceinline__ void upk2(unsigned long long v, float& x, float& y){
    asm("mov.b64 {%0,%1}, %2;" : "=f"(x), "=f"(y) : "l"(v));
}
static __device__ __forceinline__ void fma2(unsigned long long& d,
                                            unsigned long long a, unsigned long long b){
    asm("fma.rn.f32x2 %0, %1, %2, %0;" : "+l"(d) : "l"(a), "l"(b));
}

// ---------------------------------------------------------------------------
// obs -> hidden: one warp per row. out = leaky(LN(x @ obs_W + obs_b))
// ---------------------------------------------------------------------------
__global__ void obs_kernel(const float* __restrict__ xs,
                           const float* __restrict__ W,
                           const float* __restrict__ b,
                           const float* __restrict__ lng,
                           const float* __restrict__ lnb,
                           float* __restrict__ out)
{
    int row  = blockIdx.x * 8 + threadIdx.y;
    int lane = threadIdx.x;
    const float* x = xs + (size_t)row * OBSD;
    float xv[OBSD];
#pragma unroll
    for (int i = 0; i < OBSD; i++) xv[i] = x[i];

    float v[16];
    float s = 0.f, q = 0.f;
#pragma unroll
    for (int u = 0; u < 16; u++){
        int c = lane + u*32;
        float acc = b[c];
#pragma unroll
        for (int i = 0; i < OBSD; i++) acc = fmaf(xv[i], W[i*HID + c], acc);
        v[u] = acc; s += acc; q += acc*acc;
    }
#pragma unroll
    for (int off = 16; off; off >>= 1){
        s += __shfl_xor_sync(0xffffffffu, s, off);
        q += __shfl_xor_sync(0xffffffffu, q, off);
    }
    float m   = s * (1.0f/HID);
    float var = q * (1.0f/HID) - m*m;
    float inv = rsqrtf(var + 1e-5f);
#pragma unroll
    for (int u = 0; u < 16; u++){
        int c = lane + u*32;
        float val = (v[u]-m)*inv*lng[c] + lnb[c];
        out[(size_t)row*HID + c] = val >= 0.f ? val : 0.01f*val;
    }
}

// ---------------------------------------------------------------------------
// Generic K=512 GEMM, BN=512 column block, f32x2 packed accumulation.
//   EPI 0: C = leaky(LN(A@W + bias_eff))   (bias_eff = bias + tval*wlast)
//   EPI 1: C = A@W + bias                  (ldc/n0 aware: used for 1536-wide)
//   EPI 2: k = A@W + bias; RK4 combine:
//            phase<3 : kacc = (phase?kacc:0) + wk*k ; hnext = h_in + ck*k
//            phase==3: hnext = h_in + ck*(kacc + k)
// ---------------------------------------------------------------------------
#define BKK 8

template<int BM, int EPI>
__global__ void __launch_bounds__(BM*8) gemm512_kernel(
    const float* __restrict__ A,
    const float* __restrict__ W, int ldw,
    const float* __restrict__ bias,
    const float* __restrict__ wlast, float tval,
    const float* __restrict__ lng, const float* __restrict__ lnb,
    float* __restrict__ C, int ldc,
    const float* __restrict__ h_in,
    float* __restrict__ kacc,
    float* __restrict__ hnext,
    float wk, float ck, int phase)
{
    constexpr int TR = BM/8;          // thread rows
    constexpr int NT = TR*64;         // threads
    constexpr int KT = HID/BKK;       // 64 k-tiles

    __shared__ float As[2][BKK][BM+8];
    __shared__ float Bs[2][BKK][HID];
    __shared__ float red[2*TR][8][2];

    const int tid = threadIdx.x;
    const int tr  = tid >> 6, tc = tid & 63;
    const long m0 = (long)blockIdx.x * BM;
    const int n0  = blockIdx.y * HID;

    unsigned long long acc[8][4];
#pragma unroll
    for (int i = 0; i < 8; i++)
#pragma unroll
        for (int p = 0; p < 4; p++) acc[i][p] = 0ull;

    const bool aAct = tid < BM*2;
    const int ar = tid >> 1, akq = tid & 1;
    constexpr int BITER = 1024/NT;          // 1024 float4 per B tile

    float4 aReg;
    float4 bReg[BITER];

    auto ldgTile = [&](int k0){
        if (aAct) aReg = *(const float4*)(A + (m0+ar)*HID + k0 + akq*4);
#pragma unroll
        for (int it = 0; it < BITER; it++){
            int idx = tid + it*NT;
            int kk = idx >> 7, c4 = idx & 127;
            bReg[it] = *(const float4*)(W + (long)(k0+kk)*ldw + n0 + c4*4);
        }
    };
    auto stsTile = [&](int buf){
        if (aAct){
            As[buf][akq*4+0][ar] = aReg.x; As[buf][akq*4+1][ar] = aReg.y;
            As[buf][akq*4+2][ar] = aReg.z; As[buf][akq*4+3][ar] = aReg.w;
        }
#pragma unroll
        for (int it = 0; it < BITER; it++){
            int idx = tid + it*NT;
            int kk = idx >> 7, c4 = idx & 127;
            *(float4*)&Bs[buf][kk][c4*4] = bReg[it];
        }
    };

    ldgTile(0); stsTile(0); __syncthreads();

#pragma unroll 1
    for (int kt = 0; kt < KT; kt++){
        int cur = kt & 1;
        if (kt + 1 < KT) ldgTile((kt+1)*BKK);
#pragma unroll
        for (int kk = 0; kk < BKK; kk++){
            ulonglong2 b0 = *(const ulonglong2*)&Bs[cur][kk][tc*8];
            ulonglong2 b1 = *(const ulonglong2*)&Bs[cur][kk][tc*8+4];
            float4 a0 = *(const float4*)&As[cur][kk][tr*8];
            float4 a1 = *(const float4*)&As[cur][kk][tr*8+4];
            float av[8] = {a0.x,a0.y,a0.z,a0.w,a1.x,a1.y,a1.z,a1.w};
#pragma unroll
            for (int i = 0; i < 8; i++){
                unsigned long long a2 = pk2(av[i], av[i]);
                fma2(acc[i][0], a2, b0.x);
                fma2(acc[i][1], a2, b0.y);
                fma2(acc[i][2], a2, b1.x);
                fma2(acc[i][3], a2, b1.y);
            }
        }
        if (kt + 1 < KT) stsTile(cur ^ 1);
        __syncthreads();
    }

    // unpack + bias
    float v[8][8];
#pragma unroll
    for (int i = 0; i < 8; i++){
        upk2(acc[i][0], v[i][0], v[i][1]);
        upk2(acc[i][1], v[i][2], v[i][3]);
        upk2(acc[i][2], v[i][4], v[i][5]);
        upk2(acc[i][3], v[i][6], v[i][7]);
    }
    float bb[8];
#pragma unroll
    for (int j = 0; j < 8; j++){
        int c = tc*8 + j;
        float b = bias[n0 + c];
        if (EPI == 0 && wlast != nullptr) b = fmaf(tval, wlast[c], b);
        bb[j] = b;
    }
#pragma unroll
    for (int i = 0; i < 8; i++)
#pragma unroll
        for (int j = 0; j < 8; j++) v[i][j] += bb[j];

    if (EPI == 0){
        // fused LayerNorm(row over 512) + leaky relu
        float s[8], q[8];
#pragma unroll
        for (int i = 0; i < 8; i++){
            float ss = 0.f, qq = 0.f;
#pragma unroll
            for (int j = 0; j < 8; j++){ float x = v[i][j]; ss += x; qq += x*x; }
            s[i] = ss; q[i] = qq;
        }
#pragma unroll
        for (int off = 16; off; off >>= 1){
#pragma unroll
            for (int i = 0; i < 8; i++){
                s[i] += __shfl_xor_sync(0xffffffffu, s[i], off);
                q[i] += __shfl_xor_sync(0xffffffffu, q[i], off);
            }
        }
        int w = tid >> 5;
        if ((tid & 31) == 0){
#pragma unroll
            for (int i = 0; i < 8; i++){ red[w][i][0] = s[i]; red[w][i][1] = q[i]; }
        }
        __syncthreads();
#pragma unroll
        for (int i = 0; i < 8; i++){
            float S = red[tr*2][i][0] + red[tr*2+1][i][0];
            float Q = red[tr*2][i][1] + red[tr*2+1][i][1];
            float m   = S * (1.0f/HID);
            float var = Q * (1.0f/HID) - m*m;
            float inv = rsqrtf(var + 1e-5f);
            long row = m0 + tr*8 + i;
            float o[8];
#pragma unroll
            for (int j = 0; j < 8; j++){
                int c = tc*8 + j;
                float val = (v[i][j]-m)*inv*lng[c] + lnb[c];
                o[j] = val >= 0.f ? val : 0.01f*val;
            }
            *(float4*)(C + row*ldc + tc*8)     = *(float4*)&o[0];
            *(float4*)(C + row*ldc + tc*8 + 4) = *(float4*)&o[4];
        }
    } else if (EPI == 1){
#pragma unroll
        for (int i = 0; i < 8; i++){
            long row = m0 + tr*8 + i;
            *(float4*)(C + row*ldc + n0 + tc*8)     = *(float4*)&v[i][0];
            *(float4*)(C + row*ldc + n0 + tc*8 + 4) = *(float4*)&v[i][4];
        }
    } else { // EPI == 2 : RK4 combine
#pragma unroll
        for (int i = 0; i < 8; i++){
            long row = m0 + tr*8 + i;
            long idx = row*HID + tc*8;
            float hv[8];
            *(float4*)&hv[0] = *(const float4*)(h_in + idx);
            *(float4*)&hv[4] = *(const float4*)(h_in + idx + 4);
            if (phase < 3){
                float ka[8];
                if (phase > 0){
                    *(float4*)&ka[0] = *(const float4*)(kacc + idx);
                    *(float4*)&ka[4] = *(const float4*)(kacc + idx + 4);
                } else {
#pragma unroll
                    for (int j = 0; j < 8; j++) ka[j] = 0.f;
                }
                float kn[8], he[8];
#pragma unroll
                for (int j = 0; j < 8; j++){
                    kn[j] = fmaf(wk, v[i][j], ka[j]);
                    he[j] = fmaf(ck, v[i][j], hv[j]);
                }
                *(float4*)(kacc + idx)      = *(float4*)&kn[0];
                *(float4*)(kacc + idx + 4)  = *(float4*)&kn[4];
                *(float4*)(hnext + idx)     = *(float4*)&he[0];
                *(float4*)(hnext + idx + 4) = *(float4*)&he[4];
            } else {
                float ka[8], ho[8];
                *(float4*)&ka[0] = *(const float4*)(kacc + idx);
                *(float4*)&ka[4] = *(const float4*)(kacc + idx + 4);
#pragma unroll
                for (int j = 0; j < 8; j++)
                    ho[j] = fmaf(ck, ka[j] + v[i][j], hv[j]);
                *(float4*)(hnext + idx)     = *(float4*)&ho[0];
                *(float4*)(hnext + idx + 4) = *(float4*)&ho[4];
            }
        }
    }
}

// ---------------------------------------------------------------------------
// GRU pointwise gates (torch order r,z,n)
// ---------------------------------------------------------------------------
__global__ void gru_pointwise(const float* __restrict__ gi,
                              const float* __restrict__ gh,
                              const float* __restrict__ hprev,
                              float* __restrict__ hout)
{
    int idx = blockIdx.x * blockDim.x + threadIdx.x;   // 0 .. 1024*512-1
    int b = idx >> 9, j = idx & 511;
    const float* gib = gi + (size_t)b*3*HID;
    const float* ghb = gh + (size_t)b*3*HID;
    float ir = gib[j],        hr = ghb[j];
    float iz = gib[HID+j],    hz = ghb[HID+j];
    float in_ = gib[2*HID+j], hn = ghb[2*HID+j];
    float r = 1.f/(1.f + expf(-(ir+hr)));
    float z = 1.f/(1.f + expf(-(iz+hz)));
    float n = tanhf(in_ + r*hn);
    float h = hprev[idx];
    hout[idx] = (1.f - z)*n + z*h;
}

__global__ void zero_kernel(float* __restrict__ p, int n)
{
    int i = blockIdx.x * blockDim.x + threadIdx.x;
    if (i < n) p[i] = 0.f;
}

// ---------------------------------------------------------------------------
// Host driver
// ---------------------------------------------------------------------------
extern "C" void kernel_launch(void* const* d_in, const int* in_sizes, int n_in,
                              void* d_out, int out_size)
{
    (void)in_sizes; (void)n_in; (void)out_size;
    const float* xs       = (const float*)d_in[0];
    const float* obs_W    = (const float*)d_in[1];
    const float* obs_b    = (const float*)d_in[2];
    const float* obs_lng  = (const float*)d_in[3];
    const float* obs_lnb  = (const float*)d_in[4];
    const float* ode_W1   = (const float*)d_in[5];   // [513, 512]
    const float* ode_b1   = (const float*)d_in[6];
    const float* ln1g     = (const float*)d_in[7];
    const float* ln1b     = (const float*)d_in[8];
    const float* ode_W2   = (const float*)d_in[9];
    const float* ode_b2   = (const float*)d_in[10];
    const float* ln2g     = (const float*)d_in[11];
    const float* ln2b     = (const float*)d_in[12];
    const float* ode_Wout = (const float*)d_in[13];
    const float* ode_bout = (const float*)d_in[14];
    const float* W_ih     = (const float*)d_in[15];  // [512, 1536]
    const float* b_ih     = (const float*)d_in[16];
    const float* W_hh     = (const float*)d_in[17];
    const float* b_hh     = (const float*)d_in[18];
    float* out = (float*)d_out;

    float *p_h, *p_he, *p_z1, *p_z2, *p_ka, *p_gi, *p_gh, *p_hs;
    cudaGetSymbolAddress((void**)&p_h,  g_h);
    cudaGetSymbolAddress((void**)&p_he, g_heval);
    cudaGetSymbolAddress((void**)&p_z1, g_z1);
    cudaGetSymbolAddress((void**)&p_z2, g_z2);
    cudaGetSymbolAddress((void**)&p_ka, g_kacc);
    cudaGetSymbolAddress((void**)&p_gi, g_gi);
    cudaGetSymbolAddress((void**)&p_gh, g_gh);
    cudaGetSymbolAddress((void**)&p_hs, g_hst);

    // 1) obs -> hidden for all 65536 rows (RK4 initial state)
    obs_kernel<<<M_ALL/8, dim3(32,8)>>>(xs, obs_W, obs_b, obs_lng, obs_lnb, p_h);

    // 2) RK4 batched over all T*B rows
    const float dt = 0.25f;
    const float* w1last = ode_W1 + (size_t)HID*HID;   // row 512 of [513,512]
    for (int s = 0; s < 4; s++){
        float t0 = dt * (float)s;
        float te[4] = {t0, t0 + 0.5f*dt, t0 + 0.5f*dt, t0 + dt};
        float wk[4] = {1.f, 2.f, 2.f, 1.f};
        float ck[4] = {0.5f*dt, 0.5f*dt, dt, dt/6.f};
        for (int p = 0; p < 4; p++){
            const float* in = (p == 0) ? p_h : p_he;
            gemm512_kernel<64,0><<<dim3(M_ALL/64,1), 512>>>(
                in, ode_W1, HID, ode_b1, w1last, te[p], ln1g, ln1b,
                p_z1, HID, nullptr, nullptr, nullptr, 0.f, 0.f, 0);
            gemm512_kernel<64,0><<<dim3(M_ALL/64,1), 512>>>(
                p_z1, ode_W2, HID, ode_b2, nullptr, 0.f, ln2g, ln2b,
                p_z2, HID, nullptr, nullptr, nullptr, 0.f, 0.f, 0);
            gemm512_kernel<64,2><<<dim3(M_ALL/64,1), 512>>>(
                p_z2, ode_Wout, HID, ode_bout, nullptr, 0.f, nullptr, nullptr,
                nullptr, 0, p_h, p_ka, (p == 3) ? p_h : p_he, wk[p], ck[p], p);
        }
    }

    // 3) GRU input gates for all timesteps at once: gi = h_ode @ W_ih + b_ih
    gemm512_kernel<64,1><<<dim3(M_ALL/64,3), 512>>>(
        p_h, W_ih, 3*HID, b_ih, nullptr, 0.f, nullptr, nullptr,
        p_gi, 3*HID, nullptr, nullptr, nullptr, 0.f, 0.f, 0);

    // 4) Sequential GRU over T
    zero_kernel<<<(BATCH*HID + 255)/256, 256>>>(p_hs, BATCH*HID);
    for (int t = 0; t < TSTEPS; t++){
        gemm512_kernel<16,1><<<dim3(BATCH/16,3), 128>>>(
            p_hs, W_hh, 3*HID, b_hh, nullptr, 0.f, nullptr, nullptr,
            p_gh, 3*HID, nullptr, nullptr, nullptr, 0.f, 0.f, 0);
        gru_pointwise<<<(BATCH*HID)/512, 512>>>(
            p_gi + (size_t)t*BATCH*3*HID, p_gh, p_hs,
            (t == TSTEPS-1) ? out : p_hs);
    }
}

// round 2
// speedup vs baseline: 1.0507x; 1.0507x over previous
#include <cuda_runtime.h>
#include <cstdint>
#include <cstddef>

// Problem sizes
#define TSTEPS 64
#define BATCH  1024
#define OBSD   8
#define HID    512
#define M_ALL  (TSTEPS*BATCH)   // 65536

// ---------------------------------------------------------------------------
// Scratch buffers (static __device__ globals — no allocation allowed)
// ---------------------------------------------------------------------------
__device__ float g_h    [(size_t)M_ALL*HID];   // RK4 state (init = hs), ends as h_ode
__device__ float g_heval[(size_t)M_ALL*HID];   // intermediate eval point h + c*k
__device__ float g_z1   [(size_t)M_ALL*HID];
__device__ float g_z2   [(size_t)M_ALL*HID];
__device__ float g_kacc [(size_t)M_ALL*HID];
__device__ float g_gi   [(size_t)M_ALL*3*HID]; // GRU input gates for all T
__device__ float g_gh   [(size_t)BATCH*3*HID];
__device__ float g_hst  [(size_t)BATCH*HID];   // GRU recurrent state

// ---------------------------------------------------------------------------
// packed f32x2 helpers (sm_103a dual-rate fp32 path; plain FFMA is rt=2/SMSP)
// ---------------------------------------------------------------------------
static __device__ __forceinline__ unsigned long long pk2(float x, float y){
    unsigned long long r;
    asm("mov.b64 %0, {%1,%2};" : "=l"(r) : "f"(x), "f"(y));
    return r;
}
static __device__ __forceinline__ void upk2(unsigned long long v, float& x, float& y){
    asm("mov.b64 {%0,%1}, %2;" : "=f"(x), "=f"(y) : "l"(v));
}
static __device__ __forceinline__ void fma2(unsigned long long& d,
                                            unsigned long long a, unsigned long long b){
    asm("fma.rn.f32x2 %0, %1, %2, %0;" : "+l"(d) : "l"(a), "l"(b));
}

// ---------------------------------------------------------------------------
// obs -> hidden: one warp per row. out = leaky(LN(x @ obs_W + obs_b))
// ---------------------------------------------------------------------------
__global__ void obs_kernel(const float* __restrict__ xs,
                           const float* __restrict__ W,
                           const float* __restrict__ b,
                           const float* __restrict__ lng,
                           const float* __restrict__ lnb,
                           float* __restrict__ out)
{
    int row  = blockIdx.x * 8 + threadIdx.y;
    int lane = threadIdx.x;
    const float* x = xs + (size_t)row * OBSD;
    float xv[OBSD];
#pragma unroll
    for (int i = 0; i < OBSD; i++) xv[i] = x[i];

    float v[16];
    float s = 0.f, q = 0.f;
#pragma unroll
    for (int u = 0; u < 16; u++){
        int c = lane + u*32;
        float acc = b[c];
#pragma unroll
        for (int i = 0; i < OBSD; i++) acc = fmaf(xv[i], W[i*HID + c], acc);
        v[u] = acc; s += acc; q += acc*acc;
    }
#pragma unroll
    for (int off = 16; off; off >>= 1){
        s += __shfl_xor_sync(0xffffffffu, s, off);
        q += __shfl_xor_sync(0xffffffffu, q, off);
    }
    float m   = s * (1.0f/HID);
    float var = q * (1.0f/HID) - m*m;
    float inv = rsqrtf(var + 1e-5f);
#pragma unroll
    for (int u = 0; u < 16; u++){
        int c = lane + u*32;
        float val = (v[u]-m)*inv*lng[c] + lnb[c];
        out[(size_t)row*HID + c] = val >= 0.f ? val : 0.01f*val;
    }
}

// ---------------------------------------------------------------------------
// Generic K=512 GEMM, BN=512 column block, f32x2 packed accumulation.
//   EPI 0: C = leaky(LN(A@W + bias_eff))   (bias_eff = bias + tval*wlast)
//   EPI 1: C = A@W + bias                  (ldc/n0 aware: used for 1536-wide)
//   EPI 2: k = A@W + bias; RK4 combine:
//            phase<3 : kacc = (phase?kacc:0) + wk*k ; hnext = h_in + ck*k
//            phase==3: hnext = h_in + ck*(kacc + k)
// ---------------------------------------------------------------------------
#define BKK 8

template<int BM, int EPI>
__global__ void __launch_bounds__(BM*8) gemm512_kernel(
    const float* __restrict__ A,
    const float* __restrict__ W, int ldw,
    const float* __restrict__ bias,
    const float* __restrict__ wlast, float tval,
    const float* __restrict__ lng, const float* __restrict__ lnb,
    float* __restrict__ C, int ldc,
    const float* __restrict__ h_in,
    float* __restrict__ kacc,
    float* __restrict__ hnext,
    float wk, float ck, int phase)
{
    constexpr int TR = BM/8;          // thread rows
    constexpr int NT = TR*64;         // threads
    constexpr int KT = HID/BKK;       // 64 k-tiles

    __shared__ float As[2][BKK][BM+8];
    __shared__ float Bs[2][BKK][HID];
    __shared__ float red[2*TR][8][2];

    const int tid = threadIdx.x;
    const int tr  = tid >> 6, tc = tid & 63;
    const long m0 = (long)blockIdx.x * BM;
    const int n0  = blockIdx.y * HID;

    unsigned long long acc[8][4];
#pragma unroll
    for (int i = 0; i < 8; i++)
#pragma unroll
        for (int p = 0; p < 4; p++) acc[i][p] = 0ull;

    const bool aAct = tid < BM*2;
    const int ar = tid >> 1, akq = tid & 1;
    constexpr int BITER = 1024/NT;          // 1024 float4 per B tile

    float4 aReg;
    float4 bReg[BITER];

    auto ldgTile = [&](int k0){
        if (aAct) aReg = *(const float4*)(A + (m0+ar)*HID + k0 + akq*4);
#pragma unroll
        for (int it = 0; it < BITER; it++){
            int idx = tid + it*NT;
            int kk = idx >> 7, c4 = idx & 127;
            bReg[it] = *(const float4*)(W + (long)(k0+kk)*ldw + n0 + c4*4);
        }
    };
    auto stsTile = [&](int buf){
        if (aAct){
            As[buf][akq*4+0][ar] = aReg.x; As[buf][akq*4+1][ar] = aReg.y;
            As[buf][akq*4+2][ar] = aReg.z; As[buf][akq*4+3][ar] = aReg.w;
        }
#pragma unroll
        for (int it = 0; it < BITER; it++){
            int idx = tid + it*NT;
            int kk = idx >> 7, c4 = idx & 127;
            *(float4*)&Bs[buf][kk][c4*4] = bReg[it];
        }
    };

    ldgTile(0); stsTile(0); __syncthreads();

#pragma unroll 1
    for (int kt = 0; kt < KT; kt++){
        int cur = kt & 1;
        if (kt + 1 < KT) ldgTile((kt+1)*BKK);
#pragma unroll
        for (int kk = 0; kk < BKK; kk++){
            ulonglong2 b0 = *(const ulonglong2*)&Bs[cur][kk][tc*8];
            ulonglong2 b1 = *(const ulonglong2*)&Bs[cur][kk][tc*8+4];
            float4 a0 = *(const float4*)&As[cur][kk][tr*8];
            float4 a1 = *(const float4*)&As[cur][kk][tr*8+4];
            float av[8] = {a0.x,a0.y,a0.z,a0.w,a1.x,a1.y,a1.z,a1.w};
#pragma unroll
            for (int i = 0; i < 8; i++){
                unsigned long long a2 = pk2(av[i], av[i]);
                fma2(acc[i][0], a2, b0.x);
                fma2(acc[i][1], a2, b0.y);
                fma2(acc[i][2], a2, b1.x);
                fma2(acc[i][3], a2, b1.y);
            }
        }
        if (kt + 1 < KT) stsTile(cur ^ 1);
        __syncthreads();
    }

    // unpack + bias
    float v[8][8];
#pragma unroll
    for (int i = 0; i < 8; i++){
        upk2(acc[i][0], v[i][0], v[i][1]);
        upk2(acc[i][1], v[i][2], v[i][3]);
        upk2(acc[i][2], v[i][4], v[i][5]);
        upk2(acc[i][3], v[i][6], v[i][7]);
    }
    float bb[8];
#pragma unroll
    for (int j = 0; j < 8; j++){
        int c = tc*8 + j;
        float b = bias[n0 + c];
        if (EPI == 0 && wlast != nullptr) b = fmaf(tval, wlast[c], b);
        bb[j] = b;
    }
#pragma unroll
    for (int i = 0; i < 8; i++)
#pragma unroll
        for (int j = 0; j < 8; j++) v[i][j] += bb[j];

    if (EPI == 0){
        // fused LayerNorm(row over 512) + leaky relu
        float s[8], q[8];
#pragma unroll
        for (int i = 0; i < 8; i++){
            float ss = 0.f, qq = 0.f;
#pragma unroll
            for (int j = 0; j < 8; j++){ float x = v[i][j]; ss += x; qq += x*x; }
            s[i] = ss; q[i] = qq;
        }
#pragma unroll
        for (int off = 16; off; off >>= 1){
#pragma unroll
            for (int i = 0; i < 8; i++){
                s[i] += __shfl_xor_sync(0xffffffffu, s[i], off);
                q[i] += __shfl_xor_sync(0xffffffffu, q[i], off);
            }
        }
        int w = tid >> 5;
        if ((tid & 31) == 0){
#pragma unroll
            for (int i = 0; i < 8; i++){ red[w][i][0] = s[i]; red[w][i][1] = q[i]; }
        }
        __syncthreads();
#pragma unroll
        for (int i = 0; i < 8; i++){
            float S = red[tr*2][i][0] + red[tr*2+1][i][0];
            float Q = red[tr*2][i][1] + red[tr*2+1][i][1];
            float m   = S * (1.0f/HID);
            float var = Q * (1.0f/HID) - m*m;
            float inv = rsqrtf(var + 1e-5f);
            long row = m0 + tr*8 + i;
            float o[8];
#pragma unroll
            for (int j = 0; j < 8; j++){
                int c = tc*8 + j;
                float val = (v[i][j]-m)*inv*lng[c] + lnb[c];
                o[j] = val >= 0.f ? val : 0.01f*val;
            }
            *(float4*)(C + row*ldc + tc*8)     = *(float4*)&o[0];
            *(float4*)(C + row*ldc + tc*8 + 4) = *(float4*)&o[4];
        }
    } else if (EPI == 1){
#pragma unroll
        for (int i = 0; i < 8; i++){
            long row = m0 + tr*8 + i;
            *(float4*)(C + row*ldc + n0 + tc*8)     = *(float4*)&v[i][0];
            *(float4*)(C + row*ldc + n0 + tc*8 + 4) = *(float4*)&v[i][4];
        }
    } else { // EPI == 2 : RK4 combine
#pragma unroll
        for (int i = 0; i < 8; i++){
            long row = m0 + tr*8 + i;
            long idx = row*HID + tc*8;
            float hv[8];
            *(float4*)&hv[0] = *(const float4*)(h_in + idx);
            *(float4*)&hv[4] = *(const float4*)(h_in + idx + 4);
            if (phase < 3){
                float ka[8];
                if (phase > 0){
                    *(float4*)&ka[0] = *(const float4*)(kacc + idx);
                    *(float4*)&ka[4] = *(const float4*)(kacc + idx + 4);
                } else {
#pragma unroll
                    for (int j = 0; j < 8; j++) ka[j] = 0.f;
                }
                float kn[8], he[8];
#pragma unroll
                for (int j = 0; j < 8; j++){
                    kn[j] = fmaf(wk, v[i][j], ka[j]);
                    he[j] = fmaf(ck, v[i][j], hv[j]);
                }
                *(float4*)(kacc + idx)      = *(float4*)&kn[0];
                *(float4*)(kacc + idx + 4)  = *(float4*)&kn[4];
                *(float4*)(hnext + idx)     = *(float4*)&he[0];
                *(float4*)(hnext + idx + 4) = *(float4*)&he[4];
            } else {
                float ka[8], ho[8];
                *(float4*)&ka[0] = *(const float4*)(kacc + idx);
                *(float4*)&ka[4] = *(const float4*)(kacc + idx + 4);
#pragma unroll
                for (int j = 0; j < 8; j++)
                    ho[j] = fmaf(ck, ka[j] + v[i][j], hv[j]);
                *(float4*)(hnext + idx)     = *(float4*)&ho[0];
                *(float4*)(hnext + idx + 4) = *(float4*)&ho[4];
            }
        }
    }
}

// ---------------------------------------------------------------------------
// GRU pointwise gates (torch order r,z,n)
// ---------------------------------------------------------------------------
__global__ void gru_pointwise(const float* __restrict__ gi,
                              const float* __restrict__ gh,
                              const float* __restrict__ hprev,
                              float* __restrict__ hout)
{
    int idx = blockIdx.x * blockDim.x + threadIdx.x;   // 0 .. 1024*512-1
    int b = idx >> 9, j = idx & 511;
    const float* gib = gi + (size_t)b*3*HID;
    const float* ghb = gh + (size_t)b*3*HID;
    float ir = gib[j],        hr = ghb[j];
    float iz = gib[HID+j],    hz = ghb[HID+j];
    float in_ = gib[2*HID+j], hn = ghb[2*HID+j];
    float r = 1.f/(1.f + expf(-(ir+hr)));
    float z = 1.f/(1.f + expf(-(iz+hz)));
    float n = tanhf(in_ + r*hn);
    float h = hprev[idx];
    hout[idx] = (1.f - z)*n + z*h;
}

__global__ void zero_kernel(float* __restrict__ p, int n)
{
    int i = blockIdx.x * blockDim.x + threadIdx.x;
    if (i < n) p[i] = 0.f;
}

// ---------------------------------------------------------------------------
// Host driver
// ---------------------------------------------------------------------------
extern "C" void kernel_launch(void* const* d_in, const int* in_sizes, int n_in,
                              void* d_out, int out_size)
{
    (void)in_sizes; (void)n_in; (void)out_size;
    const float* xs       = (const float*)d_in[0];
    const float* obs_W    = (const float*)d_in[1];
    const float* obs_b    = (const float*)d_in[2];
    const float* obs_lng  = (const float*)d_in[3];
    const float* obs_lnb  = (const float*)d_in[4];
    const float* ode_W1   = (const float*)d_in[5];   // [513, 512]
    const float* ode_b1   = (const float*)d_in[6];
    const float* ln1g     = (const float*)d_in[7];
    const float* ln1b     = (const float*)d_in[8];
    const float* ode_W2   = (const float*)d_in[9];
    const float* ode_b2   = (const float*)d_in[10];
    const float* ln2g     = (const float*)d_in[11];
    const float* ln2b     = (const float*)d_in[12];
    const float* ode_Wout = (const float*)d_in[13];
    const float* ode_bout = (const float*)d_in[14];
    const float* W_ih     = (const float*)d_in[15];  // [512, 1536]
    const float* b_ih     = (const float*)d_in[16];
    const float* W_hh     = (const float*)d_in[17];
    const float* b_hh     = (const float*)d_in[18];
    float* out = (float*)d_out;

    float *p_h, *p_he, *p_z1, *p_z2, *p_ka, *p_gi, *p_gh, *p_hs;
    cudaGetSymbolAddress((void**)&p_h,  g_h);
    cudaGetSymbolAddress((void**)&p_he, g_heval);
    cudaGetSymbolAddress((void**)&p_z1, g_z1);
    cudaGetSymbolAddress((void**)&p_z2, g_z2);
    cudaGetSymbolAddress((void**)&p_ka, g_kacc);
    cudaGetSymbolAddress((void**)&p_gi, g_gi);
    cudaGetSymbolAddress((void**)&p_gh, g_gh);
    cudaGetSymbolAddress((void**)&p_hs, g_hst);

    // 1) obs -> hidden for all 65536 rows (RK4 initial state)
    obs_kernel<<<M_ALL/8, dim3(32,8)>>>(xs, obs_W, obs_b, obs_lng, obs_lnb, p_h);

    // 2) RK4 batched over all T*B rows
    const float dt = 0.25f;
    const float* w1last = ode_W1 + (size_t)HID*HID;   // row 512 of [513,512]
    for (int s = 0; s < 4; s++){
        float t0 = dt * (float)s;
        float te[4] = {t0, t0 + 0.5f*dt, t0 + 0.5f*dt, t0 + dt};
        float wk[4] = {1.f, 2.f, 2.f, 1.f};
        float ck[4] = {0.5f*dt, 0.5f*dt, dt, dt/6.f};
        for (int p = 0; p < 4; p++){
            const float* in = (p == 0) ? p_h : p_he;
            gemm512_kernel<64,0><<<dim3(M_ALL/64,1), 512>>>(
                in, ode_W1, HID, ode_b1, w1last, te[p], ln1g, ln1b,
                p_z1, HID, nullptr, nullptr, nullptr, 0.f, 0.f, 0);
            gemm512_kernel<64,0><<<dim3(M_ALL/64,1), 512>>>(
                p_z1, ode_W2, HID, ode_b2, nullptr, 0.f, ln2g, ln2b,
                p_z2, HID, nullptr, nullptr, nullptr, 0.f, 0.f, 0);
            gemm512_kernel<64,2><<<dim3(M_ALL/64,1), 512>>>(
                p_z2, ode_Wout, HID, ode_bout, nullptr, 0.f, nullptr, nullptr,
                nullptr, 0, p_h, p_ka, (p == 3) ? p_h : p_he, wk[p], ck[p], p);
        }
    }

    // 3) GRU input gates for all timesteps at once: gi = h_ode @ W_ih + b_ih
    gemm512_kernel<64,1><<<dim3(M_ALL/64,3), 512>>>(
        p_h, W_ih, 3*HID, b_ih, nullptr, 0.f, nullptr, nullptr,
        p_gi, 3*HID, nullptr, nullptr, nullptr, 0.f, 0.f, 0);

    // 4) Sequential GRU over T
    zero_kernel<<<(BATCH*HID + 255)/256, 256>>>(p_hs, BATCH*HID);
    for (int t = 0; t < TSTEPS; t++){
        gemm512_kernel<16,1><<<dim3(BATCH/16,3), 128>>>(
            p_hs, W_hh, 3*HID, b_hh, nullptr, 0.f, nullptr, nullptr,
            p_gh, 3*HID, nullptr, nullptr, nullptr, 0.f, 0.f, 0);
        gru_pointwise<<<(BATCH*HID)/512, 512>>>(
            p_gi + (size_t)t*BATCH*3*HID, p_gh, p_hs,
            (t == TSTEPS-1) ? out : p_hs);
    }
}

// round 4
// speedup vs baseline: 2.0662x; 1.9664x over previous
#include <cuda_runtime.h>
#include <cuda_bf16.h>
#include <cstdint>
#include <cstddef>

#define TSTEPS 64
#define BATCH  1024
#define OBSD   8
#define HID    512
#define M_ALL  (TSTEPS*BATCH)

// ---------------- scratch (__device__ globals; no allocation allowed) -------
__device__ float g_h [(size_t)M_ALL*HID];
__device__ float g_he[(size_t)M_ALL*HID];
__device__ float g_z1[(size_t)M_ALL*HID];
__device__ float g_z2[(size_t)M_ALL*HID];
__device__ float g_ka[(size_t)M_ALL*HID];
__device__ float g_gi[(size_t)M_ALL*3*HID];
__device__ float g_gh[(size_t)BATCH*3*HID];
__device__ float g_hs[(size_t)BATCH*HID];

// bf16 hi/lo split weights, transposed to [n][k] row-major (k contiguous).
__device__ __nv_bfloat16 w1_hi[512*512],  w1_lo[512*512];
__device__ __nv_bfloat16 w2_hi[512*512],  w2_lo[512*512];
__device__ __nv_bfloat16 wo_hi[512*512],  wo_lo[512*512];
__device__ __nv_bfloat16 wi_hi[1536*512], wi_lo[1536*512];
__device__ __nv_bfloat16 wh_hi[1536*512], wh_lo[1536*512];

// ---------------- helpers ---------------------------------------------------
static __device__ __forceinline__ uint32_t smem_u32(const void* p){
    uint32_t a;
    asm("{ .reg .u64 t; cvta.to.shared.u64 t, %1; cvt.u32.u64 %0, t; }" : "=r"(a) : "l"(p));
    return a;
}
static __device__ __forceinline__ void cp16(uint32_t dst, const void* src){
    asm volatile("cp.async.cg.shared.global [%0], [%1], 16;" :: "r"(dst), "l"(src) : "memory");
}
#define CP_COMMIT() asm volatile("cp.async.commit_group;" ::: "memory")

static __device__ __forceinline__ void mma16816(float* d, const uint32_t* a, const uint32_t* b){
    asm volatile(
        "mma.sync.aligned.m16n8k16.row.col.f32.bf16.bf16.f32 "
        "{%0,%1,%2,%3}, {%4,%5,%6,%7}, {%8,%9}, {%0,%1,%2,%3};"
        : "+f"(d[0]), "+f"(d[1]), "+f"(d[2]), "+f"(d[3])
        : "r"(a[0]), "r"(a[1]), "r"(a[2]), "r"(a[3]), "r"(b[0]), "r"(b[1]));
}

// ---------------- weight conversion: [K,N] fp32 -> [n][k] bf16 hi/lo --------
__global__ void conv_w(const float* __restrict__ W, int N,
                       __nv_bfloat16* __restrict__ hi, __nv_bfloat16* __restrict__ lo)
{
    int idx = blockIdx.x * 256 + threadIdx.x;
    if (idx >= 512 * N) return;
    int k = idx / N, n = idx - k * N;
    float v = W[idx];
    __nv_bfloat16 h = __float2bfloat16(v);
    __nv_bfloat16 l = __float2bfloat16(v - __bfloat162float(h));
    hi[(size_t)n*512 + k] = h;
    lo[(size_t)n*512 + k] = l;
}

// ---------------- obs -> hidden ---------------------------------------------
__global__ void obs_kernel(const float* __restrict__ xs, const float* __restrict__ W,
                           const float* __restrict__ b, const float* __restrict__ lng,
                           const float* __restrict__ lnb, float* __restrict__ out)
{
    int row  = blockIdx.x * 8 + threadIdx.y;
    int lane = threadIdx.x;
    const float* x = xs + (size_t)row * OBSD;
    float xv[OBSD];
#pragma unroll
    for (int i = 0; i < OBSD; i++) xv[i] = x[i];
    float v[16], s = 0.f, q = 0.f;
#pragma unroll
    for (int u = 0; u < 16; u++){
        int c = lane + u*32;
        float acc = b[c];
#pragma unroll
        for (int i = 0; i < OBSD; i++) acc = fmaf(xv[i], W[i*HID + c], acc);
        v[u] = acc; s += acc; q += acc*acc;
    }
#pragma unroll
    for (int off = 16; off; off >>= 1){
        s += __shfl_xor_sync(0xffffffffu, s, off);
        q += __shfl_xor_sync(0xffffffffu, q, off);
    }
    float m = s*(1.0f/HID), var = q*(1.0f/HID) - m*m;
    float inv = rsqrtf(var + 1e-5f);
#pragma unroll
    for (int u = 0; u < 16; u++){
        int c = lane + u*32;
        float val = (v[u]-m)*inv*lng[c] + lnb[c];
        out[(size_t)row*HID + c] = val >= 0.f ? val : 0.01f*val;
    }
}

// ---------------- mma.sync GEMM: C[CTAM,512] = A[CTAM,512] @ W --------------
// 8 warps, warp tile CTAM x 64. bf16 split: Ahi*Whi + Alo*Whi + Ahi*Wlo.
// smem layout (dynamic):
//   [0,2048)      bias (512 f)
//   [2048,4096)   ln gamma
//   [4096,6144)   ln beta
//   [6144,10240)  LN reduction (64 rows x 8 warps x float2)
//   [10240, ...)  2 stages: { Ahi[CTAM][40], Alo[CTAM][40], Bhi[512][40], Blo[512][40] } bf16
#define OFF_BIAS 0
#define OFF_G    2048
#define OFF_B    4096
#define OFF_RED  6144
#define OFF_ST   10240

template<int MT, int EPI>
__global__ void __launch_bounds__(256) gemm_mma(
    const float* __restrict__ A,
    const __nv_bfloat16* __restrict__ Whi, const __nv_bfloat16* __restrict__ Wlo,
    const float* __restrict__ bias, const float* __restrict__ wlast, float tval,
    const float* __restrict__ lng, const float* __restrict__ lnb,
    float* __restrict__ C, int ldc,
    const float* __restrict__ h_in, float* __restrict__ kacc, float* __restrict__ hnext,
    float wk, float ck, int phase)
{
    constexpr int CTAM = MT*16;
    constexpr int STG  = 2*CTAM*80 + 2*40960;   // bytes per stage

    extern __shared__ char sm[];
    const int tid  = threadIdx.x;
    const int w    = tid >> 5;
    const int lane = tid & 31;
    const int r0   = lane >> 2;
    const int kq   = (lane & 3) * 2;
    const size_t m0 = (size_t)blockIdx.x * CTAM;
    const int n0   = blockIdx.y * 512;
    const int nblk = blockIdx.y;

    // stage bias / LN params
    for (int i = tid; i < 512; i += 256){
        float b = bias[n0 + i];
        if (EPI == 0 && wlast != nullptr) b = fmaf(tval, wlast[i], b);
        *(float*)(sm + OFF_BIAS + i*4) = b;
        if (EPI == 0){
            *(float*)(sm + OFF_G + i*4) = lng[i];
            *(float*)(sm + OFF_B + i*4) = lnb[i];
        }
    }

    float acc[MT][8][4];
#pragma unroll
    for (int mt = 0; mt < MT; mt++)
#pragma unroll
        for (int nt = 0; nt < 8; nt++)
#pragma unroll
            for (int i = 0; i < 4; i++) acc[mt][nt][i] = 0.f;

    auto produce = [&](int c, int s){
        char* st = sm + OFF_ST + s*STG;
        const int k0 = c*32;
        // B hi/lo via cp.async (global pre-transposed [n][512] bf16)
        const char* srcH = (const char*)Whi + ((size_t)nblk*512)*1024 + (size_t)k0*2;
        const char* srcL = (const char*)Wlo + ((size_t)nblk*512)*1024 + (size_t)k0*2;
        uint32_t bh = smem_u32(st + 2*CTAM*80);
        uint32_t bl = bh + 40960;
#pragma unroll
        for (int i = 0; i < 8; i++){
            int idx = tid + i*256;
            int n = idx >> 2, q = idx & 3;
            cp16(bh + n*80 + q*16, srcH + (size_t)n*1024 + q*16);
            cp16(bl + n*80 + q*16, srcL + (size_t)n*1024 + q*16);
        }
        // A fp32 -> bf16 hi/lo
        if (tid < CTAM*4){
            int row = tid >> 2, q = tid & 3;
            const float4* src = (const float4*)(A + (m0+row)*512 + k0 + q*8);
            float4 x0 = src[0], x1 = src[1];
            float xv[8] = {x0.x,x0.y,x0.z,x0.w,x1.x,x1.y,x1.z,x1.w};
            __nv_bfloat16 h8[8], l8[8];
#pragma unroll
            for (int j = 0; j < 8; j++){
                h8[j] = __float2bfloat16(xv[j]);
                l8[j] = __float2bfloat16(xv[j] - __bfloat162float(h8[j]));
            }
            *(uint4*)(st + row*80 + q*16)           = *(uint4*)h8;
            *(uint4*)(st + CTAM*80 + row*80 + q*16) = *(uint4*)l8;
        }
    };

    auto consume = [&](int s){
        const char* st  = sm + OFF_ST + s*STG;
        const char* pAh = st;
        const char* pAl = st + CTAM*80;
        const char* pBh = st + 2*CTAM*80;
        const char* pBl = pBh + 40960;
#pragma unroll
        for (int ks = 0; ks < 2; ks++){
            const int kb = ks*16;
            const int cA  = (kb + kq)*2;
            const int cA8 = (kb + kq + 8)*2;
            uint32_t aH[MT][4], aL[MT][4], bF[8][2];
#pragma unroll
            for (int mt = 0; mt < MT; mt++){
                int rr = mt*16 + r0;
                aH[mt][0] = *(const uint32_t*)(pAh + rr*80     + cA);
                aH[mt][1] = *(const uint32_t*)(pAh + (rr+8)*80 + cA);
                aH[mt][2] = *(const uint32_t*)(pAh + rr*80     + cA8);
                aH[mt][3] = *(const uint32_t*)(pAh + (rr+8)*80 + cA8);
                aL[mt][0] = *(const uint32_t*)(pAl + rr*80     + cA);
                aL[mt][1] = *(const uint32_t*)(pAl + (rr+8)*80 + cA);
                aL[mt][2] = *(const uint32_t*)(pAl + rr*80     + cA8);
                aL[mt][3] = *(const uint32_t*)(pAl + (rr+8)*80 + cA8);
            }
#pragma unroll
            for (int nt = 0; nt < 8; nt++){
                int n = w*64 + nt*8 + r0;
                bF[nt][0] = *(const uint32_t*)(pBh + n*80 + cA);
                bF[nt][1] = *(const uint32_t*)(pBh + n*80 + cA8);
            }
#pragma unroll
            for (int mt = 0; mt < MT; mt++)
#pragma unroll
                for (int nt = 0; nt < 8; nt++) mma16816(acc[mt][nt], aH[mt], bF[nt]);
#pragma unroll
            for (int mt = 0; mt < MT; mt++)
#pragma unroll
                for (int nt = 0; nt < 8; nt++) mma16816(acc[mt][nt], aL[mt], bF[nt]);
#pragma unroll
            for (int nt = 0; nt < 8; nt++){
                int n = w*64 + nt*8 + r0;
                bF[nt][0] = *(const uint32_t*)(pBl + n*80 + cA);
                bF[nt][1] = *(const uint32_t*)(pBl + n*80 + cA8);
            }
#pragma unroll
            for (int mt = 0; mt < MT; mt++)
#pragma unroll
                for (int nt = 0; nt < 8; nt++) mma16816(acc[mt][nt], aH[mt], bF[nt]);
        }
    };

    produce(0, 0); CP_COMMIT();
#pragma unroll 1
    for (int c = 0; c < 16; c++){
        if (c < 15){
            produce(c+1, (c+1)&1); CP_COMMIT();
            asm volatile("cp.async.wait_group 1;" ::: "memory");
        } else {
            asm volatile("cp.async.wait_group 0;" ::: "memory");
        }
        __syncthreads();
        consume(c & 1);
        __syncthreads();
    }

    // ---- epilogue ----
    const float* bS = (const float*)(sm + OFF_BIAS);
#pragma unroll
    for (int mt = 0; mt < MT; mt++)
#pragma unroll
        for (int nt = 0; nt < 8; nt++){
            int cw = w*64 + nt*8 + kq;
            acc[mt][nt][0] += bS[cw];   acc[mt][nt][1] += bS[cw+1];
            acc[mt][nt][2] += bS[cw];   acc[mt][nt][3] += bS[cw+1];
        }

    if (EPI == 0){
        float S[MT][2], Q[MT][2];
#pragma unroll
        for (int mt = 0; mt < MT; mt++){
            S[mt][0]=S[mt][1]=Q[mt][0]=Q[mt][1]=0.f;
#pragma unroll
            for (int nt = 0; nt < 8; nt++){
                float a0=acc[mt][nt][0], a1=acc[mt][nt][1];
                float a2=acc[mt][nt][2], a3=acc[mt][nt][3];
                S[mt][0]+=a0+a1; Q[mt][0]+=a0*a0+a1*a1;
                S[mt][1]+=a2+a3; Q[mt][1]+=a2*a2+a3*a3;
            }
        }
#pragma unroll
        for (int off = 1; off <= 2; off <<= 1)
#pragma unroll
            for (int mt = 0; mt < MT; mt++)
#pragma unroll
                for (int h = 0; h < 2; h++){
                    S[mt][h] += __shfl_xor_sync(0xffffffffu, S[mt][h], off);
                    Q[mt][h] += __shfl_xor_sync(0xffffffffu, Q[mt][h], off);
                }
        if ((lane & 3) == 0){
#pragma unroll
            for (int mt = 0; mt < MT; mt++)
#pragma unroll
                for (int h = 0; h < 2; h++){
                    int row = mt*16 + r0 + 8*h;
                    *(float2*)(sm + OFF_RED + (row*8 + w)*8) = make_float2(S[mt][h], Q[mt][h]);
                }
        }
        __syncthreads();
        const float* gS = (const float*)(sm + OFF_G);
        const float* nS = (const float*)(sm + OFF_B);
#pragma unroll
        for (int mt = 0; mt < MT; mt++)
#pragma unroll
            for (int h = 0; h < 2; h++){
                int row = mt*16 + r0 + 8*h;
                float Ss = 0.f, Qs = 0.f;
#pragma unroll
                for (int ww = 0; ww < 8; ww++){
                    float2 rr = *(const float2*)(sm + OFF_RED + (row*8 + ww)*8);
                    Ss += rr.x; Qs += rr.y;
                }
                float mu  = Ss * (1.0f/512);
                float inv = rsqrtf(Qs*(1.0f/512) - mu*mu + 1e-5f);
#pragma unroll
                for (int nt = 0; nt < 8; nt++){
                    int cw = w*64 + nt*8 + kq;
                    int ci = h*2;
                    float v0 = (acc[mt][nt][ci]   - mu)*inv*gS[cw]   + nS[cw];
                    float v1 = (acc[mt][nt][ci+1] - mu)*inv*gS[cw+1] + nS[cw+1];
                    v0 = v0 >= 0.f ? v0 : 0.01f*v0;
                    v1 = v1 >= 0.f ? v1 : 0.01f*v1;
                    *(float2*)(C + (m0+row)*(size_t)ldc + cw) = make_float2(v0, v1);
                }
            }
    } else if (EPI == 1){
#pragma unroll
        for (int mt = 0; mt < MT; mt++)
#pragma unroll
            for (int h = 0; h < 2; h++){
                int row = mt*16 + r0 + 8*h;
#pragma unroll
                for (int nt = 0; nt < 8; nt++){
                    int cw = w*64 + nt*8 + kq;
                    int ci = h*2;
                    *(float2*)(C + (m0+row)*(size_t)ldc + n0 + cw) =
                        make_float2(acc[mt][nt][ci], acc[mt][nt][ci+1]);
                }
            }
    } else {
#pragma unroll
        for (int mt = 0; mt < MT; mt++)
#pragma unroll
            for (int h = 0; h < 2; h++){
                int row = mt*16 + r0 + 8*h;
#pragma unroll
                for (int nt = 0; nt < 8; nt++){
                    int cw = w*64 + nt*8 + kq;
                    int ci = h*2;
                    size_t idx = (m0+row)*512 + cw;
                    float k0v = acc[mt][nt][ci], k1v = acc[mt][nt][ci+1];
                    float2 hv = *(const float2*)(h_in + idx);
                    if (phase < 3){
                        float2 ka = (phase > 0) ? *(const float2*)(kacc + idx)
                                                : make_float2(0.f, 0.f);
                        *(float2*)(kacc + idx) =
                            make_float2(fmaf(wk,k0v,ka.x), fmaf(wk,k1v,ka.y));
                        *(float2*)(hnext + idx) =
                            make_float2(fmaf(ck,k0v,hv.x), fmaf(ck,k1v,hv.y));
                    } else {
                        float2 ka = *(const float2*)(kacc + idx);
                        *(float2*)(hnext + idx) =
                            make_float2(fmaf(ck, ka.x + k0v, hv.x),
                                        fmaf(ck, ka.y + k1v, hv.y));
                    }
                }
            }
    }
}

// ---------------- GRU pointwise + zero --------------------------------------
__global__ void gru_pointwise(const float* __restrict__ gi, const float* __restrict__ gh,
                              const float* __restrict__ hprev, float* __restrict__ hout)
{
    int idx = blockIdx.x * blockDim.x + threadIdx.x;
    int b = idx >> 9, j = idx & 511;
    const float* gib = gi + (size_t)b*3*HID;
    const float* ghb = gh + (size_t)b*3*HID;
    float ir = gib[j],        hr = ghb[j];
    float iz = gib[HID+j],    hz = ghb[HID+j];
    float in_ = gib[2*HID+j], hn = ghb[2*HID+j];
    float r = 1.f/(1.f + expf(-(ir+hr)));
    float z = 1.f/(1.f + expf(-(iz+hz)));
    float n = tanhf(in_ + r*hn);
    hout[idx] = (1.f - z)*n + z*hprev[idx];
}

__global__ void zero_kernel(float* __restrict__ p, int n)
{
    int i = blockIdx.x * blockDim.x + threadIdx.x;
    if (i < n) p[i] = 0.f;
}

// ---------------- host driver ----------------------------------------------
#define SMEM4 (OFF_ST + 2*(2*64*80 + 2*40960))   // 194560
#define SMEM2 (OFF_ST + 2*(2*32*80 + 2*40960))   // 184320

extern "C" void kernel_launch(void* const* d_in, const int* in_sizes, int n_in,
                              void* d_out, int out_size)
{
    (void)in_sizes; (void)n_in; (void)out_size;
    const float* xs       = (const float*)d_in[0];
    const float* obs_W    = (const float*)d_in[1];
    const float* obs_b    = (const float*)d_in[2];
    const float* obs_lng  = (const float*)d_in[3];
    const float* obs_lnb  = (const float*)d_in[4];
    const float* ode_W1   = (const float*)d_in[5];   // [513, 512]
    const float* ode_b1   = (const float*)d_in[6];
    const float* ln1g     = (const float*)d_in[7];
    const float* ln1b     = (const float*)d_in[8];
    const float* ode_W2   = (const float*)d_in[9];
    const float* ode_b2   = (const float*)d_in[10];
    const float* ln2g     = (const float*)d_in[11];
    const float* ln2b     = (const float*)d_in[12];
    const float* ode_Wout = (const float*)d_in[13];
    const float* ode_bout = (const float*)d_in[14];
    const float* W_ih     = (const float*)d_in[15];  // [512, 1536]
    const float* b_ih     = (const float*)d_in[16];
    const float* W_hh     = (const float*)d_in[17];
    const float* b_hh     = (const float*)d_in[18];
    float* out = (float*)d_out;

    float *p_h, *p_he, *p_z1, *p_z2, *p_ka, *p_gi, *p_gh, *p_hs;
    cudaGetSymbolAddress((void**)&p_h,  g_h);
    cudaGetSymbolAddress((void**)&p_he, g_he);
    cudaGetSymbolAddress((void**)&p_z1, g_z1);
    cudaGetSymbolAddress((void**)&p_z2, g_z2);
    cudaGetSymbolAddress((void**)&p_ka, g_ka);
    cudaGetSymbolAddress((void**)&p_gi, g_gi);
    cudaGetSymbolAddress((void**)&p_gh, g_gh);
    cudaGetSymbolAddress((void**)&p_hs, g_hs);

    __nv_bfloat16 *q1h,*q1l,*q2h,*q2l,*qoh,*qol,*qih,*qil,*qhh,*qhl;
    cudaGetSymbolAddress((void**)&q1h, w1_hi); cudaGetSymbolAddress((void**)&q1l, w1_lo);
    cudaGetSymbolAddress((void**)&q2h, w2_hi); cudaGetSymbolAddress((void**)&q2l, w2_lo);
    cudaGetSymbolAddress((void**)&qoh, wo_hi); cudaGetSymbolAddress((void**)&qol, wo_lo);
    cudaGetSymbolAddress((void**)&qih, wi_hi); cudaGetSymbolAddress((void**)&qil, wi_lo);
    cudaGetSymbolAddress((void**)&qhh, wh_hi); cudaGetSymbolAddress((void**)&qhl, wh_lo);

    cudaFuncSetAttribute(gemm_mma<4,0>, cudaFuncAttributeMaxDynamicSharedMemorySize, SMEM4);
    cudaFuncSetAttribute(gemm_mma<4,1>, cudaFuncAttributeMaxDynamicSharedMemorySize, SMEM4);
    cudaFuncSetAttribute(gemm_mma<4,2>, cudaFuncAttributeMaxDynamicSharedMemorySize, SMEM4);
    cudaFuncSetAttribute(gemm_mma<2,1>, cudaFuncAttributeMaxDynamicSharedMemorySize, SMEM2);

    // 0) weight split/transpose (tiny, once per launch)
    conv_w<<<(512*512 +255)/256, 256>>>(ode_W1,  512,  q1h, q1l);
    conv_w<<<(512*512 +255)/256, 256>>>(ode_W2,  512,  q2h, q2l);
    conv_w<<<(512*512 +255)/256, 256>>>(ode_Wout,512,  qoh, qol);
    conv_w<<<(512*1536+255)/256, 256>>>(W_ih,    1536, qih, qil);
    conv_w<<<(512*1536+255)/256, 256>>>(W_hh,    1536, qhh, qhl);

    // 1) obs -> hidden
    obs_kernel<<<M_ALL/8, dim3(32,8)>>>(xs, obs_W, obs_b, obs_lng, obs_lnb, p_h);

    // 2) RK4 batched over all T*B rows
    const float dt = 0.25f;
    const float* w1last = ode_W1 + (size_t)HID*HID;   // row 512 of [513,512]
    for (int s = 0; s < 4; s++){
        float t0 = dt * (float)s;
        float te[4] = {t0, t0 + 0.5f*dt, t0 + 0.5f*dt, t0 + dt};
        float wk[4] = {1.f, 2.f, 2.f, 1.f};
        float ck[4] = {0.5f*dt, 0.5f*dt, dt, dt/6.f};
        for (int p = 0; p < 4; p++){
            const float* in = (p == 0) ? p_h : p_he;
            gemm_mma<4,0><<<dim3(M_ALL/64,1), 256, SMEM4>>>(
                in, q1h, q1l, ode_b1, w1last, te[p], ln1g, ln1b,
                p_z1, HID, nullptr, nullptr, nullptr, 0.f, 0.f, 0);
            gemm_mma<4,0><<<dim3(M_ALL/64,1), 256, SMEM4>>>(
                p_z1, q2h, q2l, ode_b2, nullptr, 0.f, ln2g, ln2b,
                p_z2, HID, nullptr, nullptr, nullptr, 0.f, 0.f, 0);
            gemm_mma<4,2><<<dim3(M_ALL/64,1), 256, SMEM4>>>(
                p_z2, qoh, qol, ode_bout, nullptr, 0.f, nullptr, nullptr,
                nullptr, 0, p_h, p_ka, (p == 3) ? p_h : p_he, wk[p], ck[p], p);
        }
    }

    // 3) GRU input gates for all timesteps
    gemm_mma<4,1><<<dim3(M_ALL/64,3), 256, SMEM4>>>(
        p_h, qih, qil, b_ih, nullptr, 0.f, nullptr, nullptr,
        p_gi, 3*HID, nullptr, nullptr, nullptr, 0.f, 0.f, 0);

    // 4) Sequential GRU
    zero_kernel<<<(BATCH*HID + 255)/256, 256>>>(p_hs, BATCH*HID);
    for (int t = 0; t < TSTEPS; t++){
        gemm_mma<2,1><<<dim3(BATCH/32,3), 256, SMEM2>>>(
            p_hs, qhh, qhl, b_hh, nullptr, 0.f, nullptr, nullptr,
            p_gh, 3*HID, nullptr, nullptr, nullptr, 0.f, 0.f, 0);
        gru_pointwise<<<(BATCH*HID)/512, 512>>>(
            p_gi + (size_t)t*BATCH*3*HID, p_gh, p_hs,
            (t == TSTEPS-1) ? out : p_hs);
    }
}

// round 5
// speedup vs baseline: 2.5438x; 1.2312x over previous
#include <cuda_runtime.h>
#include <cuda_bf16.h>
#include <cstdint>
#include <cstddef>

#define TSTEPS 64
#define BATCH  1024
#define OBSD   8
#define HID    512
#define M_ALL  (TSTEPS*BATCH)

// ---------------- scratch (__device__ globals; no allocation allowed) -------
__device__ float g_h [(size_t)M_ALL*HID];
__device__ float g_he[(size_t)M_ALL*HID];
__device__ float g_z1[(size_t)M_ALL*HID];
__device__ float g_z2[(size_t)M_ALL*HID];
__device__ float g_ka[(size_t)M_ALL*HID];
__device__ float g_gi[(size_t)M_ALL*3*HID];
__device__ float g_gh[(size_t)BATCH*3*HID];
__device__ float g_hs[(size_t)BATCH*HID];

// tf32-rounded weights, transposed to [n][k=512] (k contiguous), stored as u32
__device__ uint32_t w1_t[512*512];
__device__ uint32_t w2_t[512*512];
__device__ uint32_t wo_t[512*512];
__device__ uint32_t wi_t[1536*512];
__device__ uint32_t wh_t[1536*512];

// ---------------- helpers ---------------------------------------------------
static __device__ __forceinline__ uint32_t smem_u32(const void* p){
    uint32_t a;
    asm("{ .reg .u64 t; cvta.to.shared.u64 t, %1; cvt.u32.u64 %0, t; }" : "=r"(a) : "l"(p));
    return a;
}
static __device__ __forceinline__ void cp16(uint32_t dst, const void* src){
    asm volatile("cp.async.cg.shared.global [%0], [%1], 16;" :: "r"(dst), "l"(src) : "memory");
}
#define CP_COMMIT() asm volatile("cp.async.commit_group;" ::: "memory")

static __device__ __forceinline__ uint32_t f2tf32(float f){
    uint32_t r;
    asm("cvt.rna.tf32.f32 %0, %1;" : "=r"(r) : "f"(f));
    return r;
}
static __device__ __forceinline__ void mma_tf32(float* d, const uint32_t* a, const uint32_t* b){
    asm volatile(
        "mma.sync.aligned.m16n8k8.row.col.f32.tf32.tf32.f32 "
        "{%0,%1,%2,%3}, {%4,%5,%6,%7}, {%8,%9}, {%0,%1,%2,%3};"
        : "+f"(d[0]), "+f"(d[1]), "+f"(d[2]), "+f"(d[3])
        : "r"(a[0]), "r"(a[1]), "r"(a[2]), "r"(a[3]), "r"(b[0]), "r"(b[1]));
}

// ---------------- weight conversion: [K,N] fp32 -> [n][k] tf32(u32) ---------
__global__ void conv_wt(const float* __restrict__ W, int N, uint32_t* __restrict__ out)
{
    int idx = blockIdx.x * 256 + threadIdx.x;
    if (idx >= 512 * N) return;
    int k = idx / N, n = idx - k * N;
    out[(size_t)n*512 + k] = f2tf32(W[idx]);
}

// ---------------- obs -> hidden ---------------------------------------------
__global__ void obs_kernel(const float* __restrict__ xs, const float* __restrict__ W,
                           const float* __restrict__ b, const float* __restrict__ lng,
                           const float* __restrict__ lnb, float* __restrict__ out)
{
    int row  = blockIdx.x * 8 + threadIdx.y;
    int lane = threadIdx.x;
    const float* x = xs + (size_t)row * OBSD;
    float xv[OBSD];
#pragma unroll
    for (int i = 0; i < OBSD; i++) xv[i] = x[i];
    float v[16], s = 0.f, q = 0.f;
#pragma unroll
    for (int u = 0; u < 16; u++){
        int c = lane + u*32;
        float acc = b[c];
#pragma unroll
        for (int i = 0; i < OBSD; i++) acc = fmaf(xv[i], W[i*HID + c], acc);
        v[u] = acc; s += acc; q += acc*acc;
    }
#pragma unroll
    for (int off = 16; off; off >>= 1){
        s += __shfl_xor_sync(0xffffffffu, s, off);
        q += __shfl_xor_sync(0xffffffffu, q, off);
    }
    float m = s*(1.0f/HID), var = q*(1.0f/HID) - m*m;
    float inv = rsqrtf(var + 1e-5f);
#pragma unroll
    for (int u = 0; u < 16; u++){
        int c = lane + u*32;
        float val = (v[u]-m)*inv*lng[c] + lnb[c];
        out[(size_t)row*HID + c] = val >= 0.f ? val : 0.01f*val;
    }
}

// ---------------- tf32 mma GEMM: C[CTAM,512] = A[CTAM,512] @ W --------------
// 8 warps, warp tile CTAM x 64, single tf32 pass, K chunks of 32.
// smem rows padded to 144B (36 floats) -> bank = 4*r0 + c : conflict-free.
#define OFF_BIAS 0
#define OFF_G    2048
#define OFF_B    4096
#define OFF_RED  6144
#define OFF_ST   10240
#define ROWB     144

template<int MT, int EPI>
__global__ void __launch_bounds__(256) gemm_mma(
    const float* __restrict__ A,
    const uint32_t* __restrict__ Wt,
    const float* __restrict__ bias, const float* __restrict__ wlast, float tval,
    const float* __restrict__ lng, const float* __restrict__ lnb,
    float* __restrict__ C, int ldc,
    const float* __restrict__ h_in, float* __restrict__ kacc, float* __restrict__ hnext,
    float wk, float ck, int phase)
{
    constexpr int CTAM = MT*16;
    constexpr int STG  = CTAM*ROWB + 512*ROWB;   // A tile + B tile per stage

    extern __shared__ char sm[];
    const int tid  = threadIdx.x;
    const int w    = tid >> 5;
    const int lane = tid & 31;
    const int r0   = lane >> 2;
    const int c4   = (lane & 3) * 4;       // byte offset of fragment col
    const int kq   = (lane & 3) * 2;       // epilogue col pair
    const size_t m0 = (size_t)blockIdx.x * CTAM;
    const int n0   = blockIdx.y * 512;

    for (int i = tid; i < 512; i += 256){
        float b = bias[n0 + i];
        if (EPI == 0 && wlast != nullptr) b = fmaf(tval, wlast[i], b);
        *(float*)(sm + OFF_BIAS + i*4) = b;
        if (EPI == 0){
            *(float*)(sm + OFF_G + i*4) = lng[i];
            *(float*)(sm + OFF_B + i*4) = lnb[i];
        }
    }

    float acc[MT][8][4];
#pragma unroll
    for (int mt = 0; mt < MT; mt++)
#pragma unroll
        for (int nt = 0; nt < 8; nt++)
#pragma unroll
            for (int i = 0; i < 4; i++) acc[mt][nt][i] = 0.f;

    auto produce = [&](int c, int s){
        char* st = sm + OFF_ST + s*STG;
        const int k0 = c*32;
        // B: 512 n-rows x 32 k floats via cp.async (16 per thread)
        uint32_t bsm = smem_u32(st + CTAM*ROWB);
        const uint32_t* srcB = Wt + (size_t)n0*512 + k0;
#pragma unroll
        for (int i = 0; i < 16; i++){
            int idx = tid + i*256;
            int n = idx >> 3, q = idx & 7;
            cp16(bsm + n*ROWB + q*16, srcB + (size_t)n*512 + q*4);
        }
        // A: fp32 -> tf32, padded rows
#pragma unroll
        for (int it = 0; it < MT/2; it++){
            int u = tid + it*256;
            int row = u >> 3, q = u & 7;
            float4 x = *(const float4*)(A + (m0+row)*512 + k0 + q*4);
            uint4 t;
            t.x = f2tf32(x.x); t.y = f2tf32(x.y);
            t.z = f2tf32(x.z); t.w = f2tf32(x.w);
            *(uint4*)(st + row*ROWB + q*16) = t;
        }
    };

    auto consume = [&](int s){
        const char* pA = sm + OFF_ST + s*STG;
        const char* pB = pA + CTAM*ROWB;
#pragma unroll
        for (int ks = 0; ks < 4; ks++){
            const int kb = ks*32;              // byte offset: 8 floats per kstep
            uint32_t aF[MT][4], bF[8][2];
#pragma unroll
            for (int mt = 0; mt < MT; mt++){
                const char* ba = pA + (mt*16 + r0)*ROWB + kb + c4;
                aF[mt][0] = *(const uint32_t*)(ba);
                aF[mt][1] = *(const uint32_t*)(ba + 8*ROWB);
                aF[mt][2] = *(const uint32_t*)(ba + 16);
                aF[mt][3] = *(const uint32_t*)(ba + 8*ROWB + 16);
            }
#pragma unroll
            for (int nt = 0; nt < 8; nt++){
                const char* bb = pB + (w*64 + nt*8 + r0)*ROWB + kb + c4;
                bF[nt][0] = *(const uint32_t*)(bb);
                bF[nt][1] = *(const uint32_t*)(bb + 16);
            }
#pragma unroll
            for (int mt = 0; mt < MT; mt++)
#pragma unroll
                for (int nt = 0; nt < 8; nt++) mma_tf32(acc[mt][nt], aF[mt], bF[nt]);
        }
    };

    produce(0, 0); CP_COMMIT();
#pragma unroll 1
    for (int c = 0; c < 16; c++){
        if (c < 15){
            produce(c+1, (c+1)&1); CP_COMMIT();
            asm volatile("cp.async.wait_group 1;" ::: "memory");
        } else {
            asm volatile("cp.async.wait_group 0;" ::: "memory");
        }
        __syncthreads();
        consume(c & 1);
        __syncthreads();
    }

    // ---- epilogue ----
    const float* bS = (const float*)(sm + OFF_BIAS);
#pragma unroll
    for (int mt = 0; mt < MT; mt++)
#pragma unroll
        for (int nt = 0; nt < 8; nt++){
            int cw = w*64 + nt*8 + kq;
            acc[mt][nt][0] += bS[cw];   acc[mt][nt][1] += bS[cw+1];
            acc[mt][nt][2] += bS[cw];   acc[mt][nt][3] += bS[cw+1];
        }

    if (EPI == 0){
        float S[MT][2], Q[MT][2];
#pragma unroll
        for (int mt = 0; mt < MT; mt++){
            S[mt][0]=S[mt][1]=Q[mt][0]=Q[mt][1]=0.f;
#pragma unroll
            for (int nt = 0; nt < 8; nt++){
                float a0=acc[mt][nt][0], a1=acc[mt][nt][1];
                float a2=acc[mt][nt][2], a3=acc[mt][nt][3];
                S[mt][0]+=a0+a1; Q[mt][0]+=a0*a0+a1*a1;
                S[mt][1]+=a2+a3; Q[mt][1]+=a2*a2+a3*a3;
            }
        }
#pragma unroll
        for (int off = 1; off <= 2; off <<= 1)
#pragma unroll
            for (int mt = 0; mt < MT; mt++)
#pragma unroll
                for (int h = 0; h < 2; h++){
                    S[mt][h] += __shfl_xor_sync(0xffffffffu, S[mt][h], off);
                    Q[mt][h] += __shfl_xor_sync(0xffffffffu, Q[mt][h], off);
                }
        if ((lane & 3) == 0){
#pragma unroll
            for (int mt = 0; mt < MT; mt++)
#pragma unroll
                for (int h = 0; h < 2; h++){
                    int row = mt*16 + r0 + 8*h;
                    *(float2*)(sm + OFF_RED + (row*8 + w)*8) = make_float2(S[mt][h], Q[mt][h]);
                }
        }
        __syncthreads();
        const float* gS = (const float*)(sm + OFF_G);
        const float* nS = (const float*)(sm + OFF_B);
#pragma unroll
        for (int mt = 0; mt < MT; mt++)
#pragma unroll
            for (int h = 0; h < 2; h++){
                int row = mt*16 + r0 + 8*h;
                float Ss = 0.f, Qs = 0.f;
#pragma unroll
                for (int ww = 0; ww < 8; ww++){
                    float2 rr = *(const float2*)(sm + OFF_RED + (row*8 + ww)*8);
                    Ss += rr.x; Qs += rr.y;
                }
                float mu  = Ss * (1.0f/512);
                float inv = rsqrtf(Qs*(1.0f/512) - mu*mu + 1e-5f);
#pragma unroll
                for (int nt = 0; nt < 8; nt++){
                    int cw = w*64 + nt*8 + kq;
                    int ci = h*2;
                    float v0 = (acc[mt][nt][ci]   - mu)*inv*gS[cw]   + nS[cw];
                    float v1 = (acc[mt][nt][ci+1] - mu)*inv*gS[cw+1] + nS[cw+1];
                    v0 = v0 >= 0.f ? v0 : 0.01f*v0;
                    v1 = v1 >= 0.f ? v1 : 0.01f*v1;
                    *(float2*)(C + (m0+row)*(size_t)ldc + cw) = make_float2(v0, v1);
                }
            }
    } else if (EPI == 1){
#pragma unroll
        for (int mt = 0; mt < MT; mt++)
#pragma unroll
            for (int h = 0; h < 2; h++){
                int row = mt*16 + r0 + 8*h;
#pragma unroll
                for (int nt = 0; nt < 8; nt++){
                    int cw = w*64 + nt*8 + kq;
                    int ci = h*2;
                    *(float2*)(C + (m0+row)*(size_t)ldc + n0 + cw) =
                        make_float2(acc[mt][nt][ci], acc[mt][nt][ci+1]);
                }
            }
    } else {
#pragma unroll
        for (int mt = 0; mt < MT; mt++)
#pragma unroll
            for (int h = 0; h < 2; h++){
                int row = mt*16 + r0 + 8*h;
#pragma unroll
                for (int nt = 0; nt < 8; nt++){
                    int cw = w*64 + nt*8 + kq;
                    int ci = h*2;
                    size_t idx = (m0+row)*512 + cw;
                    float k0v = acc[mt][nt][ci], k1v = acc[mt][nt][ci+1];
                    float2 hv = *(const float2*)(h_in + idx);
                    if (phase < 3){
                        float2 ka = (phase > 0) ? *(const float2*)(kacc + idx)
                                                : make_float2(0.f, 0.f);
                        *(float2*)(kacc + idx) =
                            make_float2(fmaf(wk,k0v,ka.x), fmaf(wk,k1v,ka.y));
                        *(float2*)(hnext + idx) =
                            make_float2(fmaf(ck,k0v,hv.x), fmaf(ck,k1v,hv.y));
                    } else {
                        float2 ka = *(const float2*)(kacc + idx);
                        *(float2*)(hnext + idx) =
                            make_float2(fmaf(ck, ka.x + k0v, hv.x),
                                        fmaf(ck, ka.y + k1v, hv.y));
                    }
                }
            }
    }
}

// ---------------- GRU pointwise + zero --------------------------------------
__global__ void gru_pointwise(const float* __restrict__ gi, const float* __restrict__ gh,
                              const float* __restrict__ hprev, float* __restrict__ hout)
{
    int idx = blockIdx.x * blockDim.x + threadIdx.x;
    int b = idx >> 9, j = idx & 511;
    const float* gib = gi + (size_t)b*3*HID;
    const float* ghb = gh + (size_t)b*3*HID;
    float ir = gib[j],        hr = ghb[j];
    float iz = gib[HID+j],    hz = ghb[HID+j];
    float in_ = gib[2*HID+j], hn = ghb[2*HID+j];
    float r = 1.f/(1.f + expf(-(ir+hr)));
    float z = 1.f/(1.f + expf(-(iz+hz)));
    float n = tanhf(in_ + r*hn);
    hout[idx] = (1.f - z)*n + z*hprev[idx];
}

__global__ void zero_kernel(float* __restrict__ p, int n)
{
    int i = blockIdx.x * blockDim.x + threadIdx.x;
    if (i < n) p[i] = 0.f;
}

// ---------------- host driver ----------------------------------------------
#define SMEM4 (OFF_ST + 2*(64*ROWB + 512*ROWB))   // 176128
#define SMEM2 (OFF_ST + 2*(32*ROWB + 512*ROWB))   // 166912

extern "C" void kernel_launch(void* const* d_in, const int* in_sizes, int n_in,
                              void* d_out, int out_size)
{
    (void)in_sizes; (void)n_in; (void)out_size;
    const float* xs       = (const float*)d_in[0];
    const float* obs_W    = (const float*)d_in[1];
    const float* obs_b    = (const float*)d_in[2];
    const float* obs_lng  = (const float*)d_in[3];
    const float* obs_lnb  = (const float*)d_in[4];
    const float* ode_W1   = (const float*)d_in[5];   // [513, 512]
    const float* ode_b1   = (const float*)d_in[6];
    const float* ln1g     = (const float*)d_in[7];
    const float* ln1b     = (const float*)d_in[8];
    const float* ode_W2   = (const float*)d_in[9];
    const float* ode_b2   = (const float*)d_in[10];
    const float* ln2g     = (const float*)d_in[11];
    const float* ln2b     = (const float*)d_in[12];
    const float* ode_Wout = (const float*)d_in[13];
    const float* ode_bout = (const float*)d_in[14];
    const float* W_ih     = (const float*)d_in[15];  // [512, 1536]
    const float* b_ih     = (const float*)d_in[16];
    const float* W_hh     = (const float*)d_in[17];
    const float* b_hh     = (const float*)d_in[18];
    float* out = (float*)d_out;

    float *p_h, *p_he, *p_z1, *p_z2, *p_ka, *p_gi, *p_gh, *p_hs;
    cudaGetSymbolAddress((void**)&p_h,  g_h);
    cudaGetSymbolAddress((void**)&p_he, g_he);
    cudaGetSymbolAddress((void**)&p_z1, g_z1);
    cudaGetSymbolAddress((void**)&p_z2, g_z2);
    cudaGetSymbolAddress((void**)&p_ka, g_ka);
    cudaGetSymbolAddress((void**)&p_gi, g_gi);
    cudaGetSymbolAddress((void**)&p_gh, g_gh);
    cudaGetSymbolAddress((void**)&p_hs, g_hs);

    uint32_t *q1,*q2,*qo,*qi,*qh;
    cudaGetSymbolAddress((void**)&q1, w1_t);
    cudaGetSymbolAddress((void**)&q2, w2_t);
    cudaGetSymbolAddress((void**)&qo, wo_t);
    cudaGetSymbolAddress((void**)&qi, wi_t);
    cudaGetSymbolAddress((void**)&qh, wh_t);

    cudaFuncSetAttribute(gemm_mma<4,0>, cudaFuncAttributeMaxDynamicSharedMemorySize, SMEM4);
    cudaFuncSetAttribute(gemm_mma<4,1>, cudaFuncAttributeMaxDynamicSharedMemorySize, SMEM4);
    cudaFuncSetAttribute(gemm_mma<4,2>, cudaFuncAttributeMaxDynamicSharedMemorySize, SMEM4);
    cudaFuncSetAttribute(gemm_mma<2,1>, cudaFuncAttributeMaxDynamicSharedMemorySize, SMEM2);

    // 0) weight tf32 transpose (tiny, once per launch)
    conv_wt<<<(512*512 +255)/256, 256>>>(ode_W1,  512,  q1);
    conv_wt<<<(512*512 +255)/256, 256>>>(ode_W2,  512,  q2);
    conv_wt<<<(512*512 +255)/256, 256>>>(ode_Wout,512,  qo);
    conv_wt<<<(512*1536+255)/256, 256>>>(W_ih,    1536, qi);
    conv_wt<<<(512*1536+255)/256, 256>>>(W_hh,    1536, qh);

    // 1) obs -> hidden
    obs_kernel<<<M_ALL/8, dim3(32,8)>>>(xs, obs_W, obs_b, obs_lng, obs_lnb, p_h);

    // 2) RK4 batched over all T*B rows
    const float dt = 0.25f;
    const float* w1last = ode_W1 + (size_t)HID*HID;   // row 512 of [513,512]
    for (int s = 0; s < 4; s++){
        float t0 = dt * (float)s;
        float te[4] = {t0, t0 + 0.5f*dt, t0 + 0.5f*dt, t0 + dt};
        float wk[4] = {1.f, 2.f, 2.f, 1.f};
        float ck[4] = {0.5f*dt, 0.5f*dt, dt, dt/6.f};
        for (int p = 0; p < 4; p++){
            const float* in = (p == 0) ? p_h : p_he;
            gemm_mma<4,0><<<dim3(M_ALL/64,1), 256, SMEM4>>>(
                in, q1, ode_b1, w1last, te[p], ln1g, ln1b,
                p_z1, HID, nullptr, nullptr, nullptr, 0.f, 0.f, 0);
            gemm_mma<4,0><<<dim3(M_ALL/64,1), 256, SMEM4>>>(
                p_z1, q2, ode_b2, nullptr, 0.f, ln2g, ln2b,
                p_z2, HID, nullptr, nullptr, nullptr, 0.f, 0.f, 0);
            gemm_mma<4,2><<<dim3(M_ALL/64,1), 256, SMEM4>>>(
                p_z2, qo, ode_bout, nullptr, 0.f, nullptr, nullptr,
                nullptr, 0, p_h, p_ka, (p == 3) ? p_h : p_he, wk[p], ck[p], p);
        }
    }

    // 3) GRU input gates for all timesteps
    gemm_mma<4,1><<<dim3(M_ALL/64,3), 256, SMEM4>>>(
        p_h, qi, b_ih, nullptr, 0.f, nullptr, nullptr,
        p_gi, 3*HID, nullptr, nullptr, nullptr, 0.f, 0.f, 0);

    // 4) Sequential GRU
    zero_kernel<<<(BATCH*HID + 255)/256, 256>>>(p_hs, BATCH*HID);
    for (int t = 0; t < TSTEPS; t++){
        gemm_mma<2,1><<<dim3(BATCH/32,3), 256, SMEM2>>>(
            p_hs, qh, b_hh, nullptr, 0.f, nullptr, nullptr,
            p_gh, 3*HID, nullptr, nullptr, nullptr, 0.f, 0.f, 0);
        gru_pointwise<<<(BATCH*HID)/512, 512>>>(
            p_gi + (size_t)t*BATCH*3*HID, p_gh, p_hs,
            (t == TSTEPS-1) ? out : p_hs);
    }
}